// round 6
// baseline (speedup 1.0000x reference)
#include <cuda_runtime.h>
#include <cuda_bf16.h>
#include <stdint.h>

// Problem constants (fixed by setup_inputs)
#define BATCH 1024
#define TLEN  512
#define NTAGS 64
#define START_TAG 62
#define STOP_TAG  63
#define FBPC  16      // batches per forward CTA (mma M dimension)
#define EMPAD 68      // padded emission row stride (floats): %4==0, bank-rotating

// Scratch (no cudaMalloc allowed)
__device__ float g_logZ[BATCH];
__device__ float g_gold[BATCH];
__device__ int   g_tags_is64;

// ---------------------------------------------------------------------------
// helpers
// ---------------------------------------------------------------------------
static __device__ __forceinline__ uint32_t pack_bf16(float lo, float hi) {
    __nv_bfloat162 h = __floats2bfloat162_rn(lo, hi);
    return *reinterpret_cast<uint32_t*>(&h);
}
static __device__ __forceinline__ float2 unpack_bf16(uint32_t u) {
    __nv_bfloat162 h = *reinterpret_cast<__nv_bfloat162*>(&u);
    return __bfloat1622float2(h);
}
static __device__ __forceinline__ uint32_t mul_bf16x2(uint32_t a, uint32_t s2) {
    __nv_bfloat162 ha = *reinterpret_cast<__nv_bfloat162*>(&a);
    __nv_bfloat162 hs = *reinterpret_cast<__nv_bfloat162*>(&s2);
    __nv_bfloat162 hc = __hmul2(ha, hs);
    return *reinterpret_cast<uint32_t*>(&hc);
}
// D(f32,m16n8) += A(bf16,m16k16,row) * B(bf16,k16n8,col)
static __device__ __forceinline__ void mma_bf16(
    float& d0, float& d1, float& d2, float& d3,
    uint32_t a0, uint32_t a1, uint32_t a2, uint32_t a3,
    uint32_t b0, uint32_t b1)
{
    asm volatile(
        "mma.sync.aligned.m16n8k16.row.col.f32.bf16.bf16.f32 "
        "{%0,%1,%2,%3}, {%4,%5,%6,%7}, {%8,%9}, {%0,%1,%2,%3};"
        : "+f"(d0), "+f"(d1), "+f"(d2), "+f"(d3)
        : "r"(a0), "r"(a1), "r"(a2), "r"(a3), "r"(b0), "r"(b1));
}

// ---------------------------------------------------------------------------
// Detect tags dtype at runtime (JAX silently downcasts int64 -> int32).
// ---------------------------------------------------------------------------
__global__ void crf_detect_kernel(const int* __restrict__ tags32)
{
    const int tid = threadIdx.x;
    int v = 0;
    for (int i = tid; i < 512; i += 32)
        v |= tags32[2 * i + 1];
#pragma unroll
    for (int off = 16; off; off >>= 1)
        v |= __shfl_xor_sync(0xffffffffu, v, off);
    if (tid == 0) g_tags_is64 = (v == 0) ? 1 : 0;
}

// ---------------------------------------------------------------------------
// Forward kernel, tensor-core version.
// grid = 64 CTAs x 128 threads (4 warps). CTA owns 16 batch rows.
// warp w computes n-tiles {2w, 2w+1} of D = P(16x64) @ E(64x64) per step;
// lane-local D values ARE the A-fragment values for k-tile w of the next
// step (after x exp(emission), cvt bf16). k-tiles exchanged via 16B/lane smem.
// p carried as bf16 A-fragments (f32 accumulate in mma). Scaled-linear
// recursion with per-CTA shared power-of-2 renorm every 8 steps.
// ---------------------------------------------------------------------------
__global__ __launch_bounds__(128, 1)
void crf_forward_mma_kernel(const float* __restrict__ em,
                            const float* __restrict__ trans,
                            const int*   __restrict__ mask)
{
    __shared__ __align__(16) uint32_t Aex[2][4][32][4];   // [buf][ktile][lane][reg]
    __shared__ __align__(16) float    em_sh[2][FBPC][EMPAD];
    __shared__ uint32_t mask_sh[TLEN];                    // bit r = mask[row r][t]
    __shared__ float    Red[4];

    const int tid  = threadIdx.x;
    const int w    = tid >> 5;          // warp 0..3
    const int lane = tid & 31;
    const int q    = lane & 3;          // thread-in-group
    const int r    = lane >> 2;         // row group 0..7
    const int b0   = blockIdx.x * FBPC;

    // ---- stage mask bits: mask_sh[t] bit row ----
    {
        uint32_t bits[4] = {0, 0, 0, 0};
        for (int row = 0; row < FBPC; row++) {
            const int* mrow = mask + (size_t)(b0 + row) * TLEN + tid * 4;
#pragma unroll
            for (int c = 0; c < 4; c++)
                bits[c] |= (uint32_t)(mrow[c] != 0) << row;
        }
#pragma unroll
        for (int c = 0; c < 4; c++)
            mask_sh[tid * 4 + c] = bits[c];
    }

    // ---- stage emissions for t = 0 ----
    {
        const int rr = tid >> 3, c8 = (tid & 7) * 8;
        const float* gp = em + ((size_t)(b0 + rr) * TLEN + 0) * NTAGS + c8;
        *(float4*)&em_sh[0][rr][c8]     = *(const float4*)gp;
        *(float4*)&em_sh[0][rr][c8 + 4] = *(const float4*)(gp + 4);
    }

    // ---- E (B-operand) fragments: Eb[kt][nn][2], nt = 2w+nn ----
    // B[k][n] = exp(trans[k][n]); exp(-10000) -> 0 kills forbidden transitions.
    uint32_t Eb[4][2][2];
#pragma unroll
    for (int kt = 0; kt < 4; kt++) {
#pragma unroll
        for (int nn = 0; nn < 2; nn++) {
            const int n  = 8 * (2 * w + nn) + r;
            const int k0 = 16 * kt + 2 * q;
            Eb[kt][nn][0] = pack_bf16(expf(trans[(k0)     * NTAGS + n]),
                                      expf(trans[(k0 + 1) * NTAGS + n]));
            Eb[kt][nn][1] = pack_bf16(expf(trans[(k0 + 8) * NTAGS + n]),
                                      expf(trans[(k0 + 9) * NTAGS + n]));
        }
    }

    // ---- A fragments (p as bf16): start state = 1 at tag 62 ----
    // k=62 -> kt=3, local k'=14 = 8+2q with q=3, low half of regs 2/3.
    uint32_t A[4][4];
#pragma unroll
    for (int kt = 0; kt < 4; kt++)
#pragma unroll
        for (int x = 0; x < 4; x++) A[kt][x] = 0u;
    if (q == 3) {
        const uint32_t one = pack_bf16(1.0f, 0.0f);
        A[3][2] = one;   // row r
        A[3][3] = one;   // row r+8
    }

    float s = 0.0f;                       // shared log-scale (same in all threads)
    const int cA = 16 * w + 2 * q;        // D cols of n-tile 2w
    const int cB = cA + 8;                // D cols of n-tile 2w+1

    __syncthreads();

    for (int t = 0; t < TLEN; ++t) {
        const int buf    = t & 1;
        const bool renorm = ((t & 7) == 7);

        // emissions for this step (register-local gather from padded smem)
        const float2 e0A = *(const float2*)&em_sh[buf][r][cA];
        const float2 e0B = *(const float2*)&em_sh[buf][r][cB];
        const float2 e1A = *(const float2*)&em_sh[buf][r + 8][cA];
        const float2 e1B = *(const float2*)&em_sh[buf][r + 8][cB];
        const uint32_t mb = mask_sh[t];
        const uint32_t m0 = (mb >> r) & 1u, m1 = (mb >> (r + 8)) & 1u;

        // prefetch emissions for t+1 into the other buffer
        const int tt = (t + 1 < TLEN) ? t + 1 : TLEN - 1;
        const int rr = tid >> 3, c8 = (tid & 7) * 8;
        const float* gp = em + ((size_t)(b0 + rr) * TLEN + tt) * NTAGS + c8;
        const float4 pf0 = *(const float4*)gp;
        const float4 pf1 = *(const float4*)(gp + 4);

        // ---- D = P @ E for this warp's two n-tiles ----
        float d00 = 0.f, d01 = 0.f, d02 = 0.f, d03 = 0.f;   // n-tile 2w
        float d10 = 0.f, d11 = 0.f, d12 = 0.f, d13 = 0.f;   // n-tile 2w+1
#pragma unroll
        for (int kt = 0; kt < 4; kt++) {
            mma_bf16(d00, d01, d02, d03,
                     A[kt][0], A[kt][1], A[kt][2], A[kt][3],
                     Eb[kt][0][0], Eb[kt][0][1]);
            mma_bf16(d10, d11, d12, d13,
                     A[kt][0], A[kt][1], A[kt][2], A[kt][3],
                     Eb[kt][1][0], Eb[kt][1][1]);
        }

        // ---- p_new = D * exp(em) ----
        const float p00 = d00 * __expf(e0A.x), p01 = d01 * __expf(e0A.y);
        const float p02 = d02 * __expf(e1A.x), p03 = d03 * __expf(e1A.y);
        const float p10 = d10 * __expf(e0B.x), p11 = d11 * __expf(e0B.y);
        const float p12 = d12 * __expf(e1B.x), p13 = d13 * __expf(e1B.y);

        if (renorm) {
            float mx = fmaxf(fmaxf(fmaxf(p00, p01), fmaxf(p02, p03)),
                             fmaxf(fmaxf(p10, p11), fmaxf(p12, p13)));
#pragma unroll
            for (int off = 16; off; off >>= 1)
                mx = fmaxf(mx, __shfl_xor_sync(0xffffffffu, mx, off));
            if (lane == 0) Red[w] = mx;
        }

        // ---- D->A relayout (register-local) + exchange k-tiles via smem ----
        // warp w's D values = A-fragment regs of k-tile kt=w for next step.
        uint32_t* dst = Aex[buf][w][lane];
        *(uint4*)dst = make_uint4(pack_bf16(p00, p01),   // row r,   k lo
                                  pack_bf16(p02, p03),   // row r+8, k lo
                                  pack_bf16(p10, p11),   // row r,   k hi
                                  pack_bf16(p12, p13));  // row r+8, k hi

        // store emission prefetch
        *(float4*)&em_sh[buf ^ 1][rr][c8]     = pf0;
        *(float4*)&em_sh[buf ^ 1][rr][c8 + 4] = pf1;

        __syncthreads();

        // gather all 4 k-tiles, apply mask select per batch row
#pragma unroll
        for (int kt = 0; kt < 4; kt++) {
            const uint4 nv = *(const uint4*)Aex[buf][kt][lane];
            A[kt][0] = m0 ? nv.x : A[kt][0];
            A[kt][1] = m1 ? nv.y : A[kt][1];
            A[kt][2] = m0 ? nv.z : A[kt][2];
            A[kt][3] = m1 ? nv.w : A[kt][3];
        }

        if (renorm) {
            const float rmax = fmaxf(fmaxf(Red[0], Red[1]), fmaxf(Red[2], Red[3]));
            int c; frexpf(rmax, &c);                    // rmax = m * 2^c
            const float sc = ldexpf(1.0f, -c);          // exact power of two
            s += (float)c * 0.6931471805599453f;
            const uint32_t sc2 = pack_bf16(sc, sc);
#pragma unroll
            for (int kt = 0; kt < 4; kt++)
#pragma unroll
                for (int x = 0; x < 4; x++)
                    A[kt][x] = mul_bf16x2(A[kt][x], sc2);
        }
    }

    // ---- epilogue: logZ[b] = s + ln( sum_j p[b][j] * exp(trans[j][STOP]) ) ----
    // After the exchange every warp holds the full P tile; warp 0 finishes.
    if (w == 0) {
        float sr = 0.0f, sr8 = 0.0f;
#pragma unroll
        for (int kt = 0; kt < 4; kt++) {
#pragma unroll
            for (int part = 0; part < 2; part++) {
                const int k0 = 16 * kt + 8 * part + 2 * q;
                const float es0 = expf(trans[(k0)     * NTAGS + STOP_TAG]);
                const float es1 = expf(trans[(k0 + 1) * NTAGS + STOP_TAG]);
                const float2 vr  = unpack_bf16(A[kt][part * 2]);
                const float2 vr8 = unpack_bf16(A[kt][part * 2 + 1]);
                sr  += vr.x  * es0 + vr.y  * es1;
                sr8 += vr8.x * es0 + vr8.y * es1;
            }
        }
        // reduce over the 4 q-lanes of each row group
#pragma unroll
        for (int off = 1; off < 4; off <<= 1) {
            sr  += __shfl_xor_sync(0xffffffffu, sr,  off);
            sr8 += __shfl_xor_sync(0xffffffffu, sr8, off);
        }
        if (q == 0) {
            g_logZ[b0 + r]     = s + logf(sr);
            g_logZ[b0 + r + 8] = s + logf(sr8);
        }
    }
}

// ---------------------------------------------------------------------------
// Gold-score kernel: one warp per batch; warp-scan for "last valid prev tag".
// Dtype-agnostic tags load (int32 vs int64).
// ---------------------------------------------------------------------------
__global__ void crf_gold_kernel(const float* __restrict__ em,
                                const float* __restrict__ trans,
                                const void* __restrict__ tags_raw,
                                const int* __restrict__ mask)
{
    const int gw   = (blockIdx.x * blockDim.x + threadIdx.x) >> 5;
    const int lane = threadIdx.x & 31;
    if (gw >= BATCH) return;
    const int b = gw;
    const int is64 = g_tags_is64;
    const long long* tags64 = (const long long*)tags_raw;
    const int*       tags32 = (const int*)tags_raw;

    float acc = 0.0f;
    int carry = START_TAG;

    for (int base = 0; base < TLEN; base += 32) {
        const int t = base + lane;
        const size_t idx = (size_t)b * TLEN + t;
        const int tag = is64 ? (int)tags64[idx] : tags32[idx];
        const int m   = mask[idx];
        const float e = em[(size_t)b * TLEN * NTAGS + (size_t)t * NTAGS + tag];

        int inc = m ? tag : -1;                 // inclusive "last valid tag" scan
#pragma unroll
        for (int off = 1; off < 32; off <<= 1) {
            int o = __shfl_up_sync(0xffffffffu, inc, off);
            if (lane >= off && inc < 0) inc = o;
        }
        int prevv = __shfl_up_sync(0xffffffffu, inc, 1);
        int prev  = (lane == 0 || prevv < 0) ? carry : prevv;

        if (m) acc += e + trans[prev * NTAGS + tag];

        int last = __shfl_sync(0xffffffffu, inc, 31);
        if (last >= 0) carry = last;
    }
#pragma unroll
    for (int off = 16; off; off >>= 1)
        acc += __shfl_xor_sync(0xffffffffu, acc, off);
    if (lane == 0)
        g_gold[b] = acc + trans[carry * NTAGS + STOP_TAG];
}

// ---------------------------------------------------------------------------
// Final reduction: mean(logZ - gold) -> d_out[0]
// ---------------------------------------------------------------------------
__global__ void crf_reduce_kernel(float* __restrict__ out)
{
    __shared__ float sh[256];
    const int tid = threadIdx.x;
    float a = 0.0f;
    for (int i = tid; i < BATCH; i += 256)
        a += g_logZ[i] - g_gold[i];
    sh[tid] = a;
    __syncthreads();
    for (int st = 128; st; st >>= 1) {
        if (tid < st) sh[tid] += sh[tid + st];
        __syncthreads();
    }
    if (tid == 0) out[0] = sh[0] / (float)BATCH;
}

// ---------------------------------------------------------------------------
extern "C" void kernel_launch(void* const* d_in, const int* in_sizes, int n_in,
                              void* d_out, int out_size)
{
    const float* em    = (const float*)d_in[0];   // (1024, 512, 64) f32
    const float* trans = (const float*)d_in[1];   // (64, 64) f32
    const void*  tags  = d_in[2];                 // (1024, 512) i32 or i64
    const int*   mask  = (const int*)d_in[3];     // (1024, 512) i32
    float* out = (float*)d_out;

    crf_detect_kernel<<<1, 32>>>((const int*)tags);
    crf_gold_kernel<<<BATCH / 8, 256>>>(em, trans, tags, mask);
    crf_forward_mma_kernel<<<BATCH / FBPC, 128>>>(em, trans, mask);
    crf_reduce_kernel<<<1, 256>>>(out);
}

// round 9
// speedup vs baseline: 1.8161x; 1.8161x over previous
#include <cuda_runtime.h>
#include <cuda_bf16.h>
#include <stdint.h>

// Problem constants (fixed by setup_inputs)
#define BATCH 1024
#define TLEN  512
#define NTAGS 64
#define START_TAG 62
#define STOP_TAG  63
#define FBPC  16      // batches per forward CTA (mma M dimension)

// Scratch (no cudaMalloc allowed)
__device__ float g_logZ[BATCH];
__device__ float g_gold[BATCH];
__device__ int   g_tags_is64;

// ---------------------------------------------------------------------------
// helpers
// ---------------------------------------------------------------------------
static __device__ __forceinline__ uint32_t pack_bf16(float lo, float hi) {
    __nv_bfloat162 h = __floats2bfloat162_rn(lo, hi);
    return *reinterpret_cast<uint32_t*>(&h);
}
static __device__ __forceinline__ float2 unpack_bf16(uint32_t u) {
    __nv_bfloat162 h = *reinterpret_cast<__nv_bfloat162*>(&u);
    return __bfloat1622float2(h);
}
static __device__ __forceinline__ uint32_t mul_bf16x2(uint32_t a, uint32_t s2) {
    __nv_bfloat162 ha = *reinterpret_cast<__nv_bfloat162*>(&a);
    __nv_bfloat162 hs = *reinterpret_cast<__nv_bfloat162*>(&s2);
    __nv_bfloat162 hc = __hmul2(ha, hs);
    return *reinterpret_cast<uint32_t*>(&hc);
}
// D(f32,m16n8) += A(bf16,m16k16,row) * B(bf16,k16n8,col)
static __device__ __forceinline__ void mma_bf16(
    float& d0, float& d1, float& d2, float& d3,
    uint32_t a0, uint32_t a1, uint32_t a2, uint32_t a3,
    uint32_t b0, uint32_t b1)
{
    asm volatile(
        "mma.sync.aligned.m16n8k16.row.col.f32.bf16.bf16.f32 "
        "{%0,%1,%2,%3}, {%4,%5,%6,%7}, {%8,%9}, {%0,%1,%2,%3};"
        : "+f"(d0), "+f"(d1), "+f"(d2), "+f"(d3)
        : "r"(a0), "r"(a1), "r"(a2), "r"(a3), "r"(b0), "r"(b1));
}

// ---------------------------------------------------------------------------
// Detect tags dtype at runtime (JAX silently downcasts int64 -> int32).
// ---------------------------------------------------------------------------
__global__ void crf_detect_kernel(const int* __restrict__ tags32)
{
    const int tid = threadIdx.x;
    int v = 0;
    for (int i = tid; i < 512; i += 32)
        v |= tags32[2 * i + 1];
#pragma unroll
    for (int off = 16; off; off >>= 1)
        v |= __shfl_xor_sync(0xffffffffu, v, off);
    if (tid == 0) g_tags_is64 = (v == 0) ? 1 : 0;
}

// ---------------------------------------------------------------------------
// Forward kernel: tensor-core recursion with register-pipelined emissions.
// grid = 64 CTAs x 128 threads. CTA owns 16 batch rows.
// warp w computes n-tiles {2w, 2w+1} of D = P(16x64) @ E(64x64) per step;
// lane-local D values ARE the A-fragment regs of k-tile w of the next step.
// k-tiles exchanged via 16B/lane smem (double-buffered, 1 barrier/step).
// Emissions: each thread LDGs its own 4 float2 for step t+4 into a 4-slot
// register ring at step t -> DRAM latency hidden across 4 barriers, no smem.
// Per-CTA power-of-2 renorm every 8 steps.
// ---------------------------------------------------------------------------
__global__ __launch_bounds__(128, 1)
void crf_forward_mma_kernel(const float* __restrict__ em,
                            const float* __restrict__ trans,
                            const int*   __restrict__ mask)
{
    __shared__ __align__(16) uint32_t Aex[2][4][32][4];   // [buf][ktile][lane][reg]
    __shared__ uint32_t mask_sh[TLEN];                    // bit r = mask[row r][t]
    __shared__ float    Red[4];

    const int tid  = threadIdx.x;
    const int w    = tid >> 5;          // warp 0..3
    const int lane = tid & 31;
    const int q    = lane & 3;          // thread-in-group
    const int r    = lane >> 2;         // row group 0..7
    const int b0   = blockIdx.x * FBPC;

    // ---- stage mask bits: mask_sh[t] bit r = mask[b0+r][t] ----
    {
        uint32_t bits[4] = {0, 0, 0, 0};
        for (int row = 0; row < FBPC; row++) {
            const int* mrow = mask + (size_t)(b0 + row) * TLEN + tid * 4;
#pragma unroll
            for (int c = 0; c < 4; c++)
                bits[c] |= (uint32_t)(mrow[c] != 0) << row;
        }
#pragma unroll
        for (int c = 0; c < 4; c++)
            mask_sh[tid * 4 + c] = bits[c];
    }

    const int cA = 16 * w + 2 * q;      // this thread's D cols (n-tile 2w)
    const int cB = cA + 8;              // n-tile 2w+1

    // ---- emission base pointers for this thread's 4 float2 per step ----
    const float* p0A = em + (size_t)(b0 + r)     * TLEN * NTAGS + cA;
    const float* p0B = em + (size_t)(b0 + r)     * TLEN * NTAGS + cB;
    const float* p1A = em + (size_t)(b0 + r + 8) * TLEN * NTAGS + cA;
    const float* p1B = em + (size_t)(b0 + r + 8) * TLEN * NTAGS + cB;

    // ---- prime register ring with steps 0..3 ----
    float2 pipe[4][4];
#pragma unroll
    for (int d = 0; d < 4; d++) {
        pipe[d][0] = *(const float2*)(p0A + (size_t)d * NTAGS);
        pipe[d][1] = *(const float2*)(p0B + (size_t)d * NTAGS);
        pipe[d][2] = *(const float2*)(p1A + (size_t)d * NTAGS);
        pipe[d][3] = *(const float2*)(p1B + (size_t)d * NTAGS);
    }

    // ---- E (B-operand) fragments: Eb[kt][nn][2], n-tile = 2w+nn ----
    uint32_t Eb[4][2][2];
#pragma unroll
    for (int kt = 0; kt < 4; kt++) {
#pragma unroll
        for (int nn = 0; nn < 2; nn++) {
            const int n  = 8 * (2 * w + nn) + r;
            const int k0 = 16 * kt + 2 * q;
            Eb[kt][nn][0] = pack_bf16(expf(trans[(k0)     * NTAGS + n]),
                                      expf(trans[(k0 + 1) * NTAGS + n]));
            Eb[kt][nn][1] = pack_bf16(expf(trans[(k0 + 8) * NTAGS + n]),
                                      expf(trans[(k0 + 9) * NTAGS + n]));
        }
    }

    // ---- A fragments (p as bf16): start state = 1 at tag 62 ----
    uint32_t A[4][4];
#pragma unroll
    for (int kt = 0; kt < 4; kt++)
#pragma unroll
        for (int x = 0; x < 4; x++) A[kt][x] = 0u;
    if (q == 3) {
        const uint32_t one = pack_bf16(1.0f, 0.0f);
        A[3][2] = one;   // row r
        A[3][3] = one;   // row r+8
    }

    float s = 0.0f;                     // shared log-scale

    __syncthreads();                    // mask staged

    for (int t0 = 0; t0 < TLEN; t0 += 8) {
#pragma unroll
        for (int ts = 0; ts < 8; ts++) {
            const int t    = t0 + ts;
            const int slot = ts & 3;          // static ring index
            const int abuf = t & 1;

            // emissions for this step (from register ring)
            const float2 e0A = pipe[slot][0];
            const float2 e0B = pipe[slot][1];
            const float2 e1A = pipe[slot][2];
            const float2 e1B = pipe[slot][3];

            // refill slot with step t+4 (clamped tail reload is harmless)
            {
                const size_t tp = (size_t)((t + 4 < TLEN) ? t + 4 : TLEN - 1) * NTAGS;
                pipe[slot][0] = *(const float2*)(p0A + tp);
                pipe[slot][1] = *(const float2*)(p0B + tp);
                pipe[slot][2] = *(const float2*)(p1A + tp);
                pipe[slot][3] = *(const float2*)(p1B + tp);
            }

            const uint32_t mb = mask_sh[t];
            const uint32_t m0 = (mb >> r) & 1u, m1 = (mb >> (r + 8)) & 1u;

            // ---- D = P @ E for this warp's two n-tiles ----
            float d00 = 0.f, d01 = 0.f, d02 = 0.f, d03 = 0.f;
            float d10 = 0.f, d11 = 0.f, d12 = 0.f, d13 = 0.f;
#pragma unroll
            for (int kt = 0; kt < 4; kt++) {
                mma_bf16(d00, d01, d02, d03,
                         A[kt][0], A[kt][1], A[kt][2], A[kt][3],
                         Eb[kt][0][0], Eb[kt][0][1]);
                mma_bf16(d10, d11, d12, d13,
                         A[kt][0], A[kt][1], A[kt][2], A[kt][3],
                         Eb[kt][1][0], Eb[kt][1][1]);
            }

            // ---- p_new = D * exp(em) ----
            const float p00 = d00 * __expf(e0A.x), p01 = d01 * __expf(e0A.y);
            const float p02 = d02 * __expf(e1A.x), p03 = d03 * __expf(e1A.y);
            const float p10 = d10 * __expf(e0B.x), p11 = d11 * __expf(e0B.y);
            const float p12 = d12 * __expf(e1B.x), p13 = d13 * __expf(e1B.y);

            const bool renorm = (ts == 7);
            if (renorm) {
                float mx = fmaxf(fmaxf(fmaxf(p00, p01), fmaxf(p02, p03)),
                                 fmaxf(fmaxf(p10, p11), fmaxf(p12, p13)));
#pragma unroll
                for (int off = 16; off; off >>= 1)
                    mx = fmaxf(mx, __shfl_xor_sync(0xffffffffu, mx, off));
                if (lane == 0) Red[w] = mx;
            }

            // ---- D->A relayout (register-local) + k-tile exchange ----
            *(uint4*)Aex[abuf][w][lane] =
                make_uint4(pack_bf16(p00, p01), pack_bf16(p02, p03),
                           pack_bf16(p10, p11), pack_bf16(p12, p13));

            __syncthreads();

#pragma unroll
            for (int kt = 0; kt < 4; kt++) {
                const uint4 nv = *(const uint4*)Aex[abuf][kt][lane];
                A[kt][0] = m0 ? nv.x : A[kt][0];
                A[kt][1] = m1 ? nv.y : A[kt][1];
                A[kt][2] = m0 ? nv.z : A[kt][2];
                A[kt][3] = m1 ? nv.w : A[kt][3];
            }

            if (renorm) {
                const float rmax = fmaxf(fmaxf(Red[0], Red[1]), fmaxf(Red[2], Red[3]));
                int cc; frexpf(rmax, &cc);                 // rmax = m * 2^cc
                const float sc = ldexpf(1.0f, -cc);        // exact power of two
                s += (float)cc * 0.6931471805599453f;
                const uint32_t sc2 = pack_bf16(sc, sc);
#pragma unroll
                for (int kt = 0; kt < 4; kt++)
#pragma unroll
                    for (int x = 0; x < 4; x++)
                        A[kt][x] = mul_bf16x2(A[kt][x], sc2);
            }
        }
    }

    // ---- epilogue: logZ[b] = s + ln( sum_j p[b][j] * exp(trans[j][STOP]) ) ----
    if (w == 0) {
        float sr = 0.0f, sr8 = 0.0f;
#pragma unroll
        for (int kt = 0; kt < 4; kt++) {
#pragma unroll
            for (int part = 0; part < 2; part++) {
                const int k0 = 16 * kt + 8 * part + 2 * q;
                const float es0 = expf(trans[(k0)     * NTAGS + STOP_TAG]);
                const float es1 = expf(trans[(k0 + 1) * NTAGS + STOP_TAG]);
                const float2 vr  = unpack_bf16(A[kt][part * 2]);
                const float2 vr8 = unpack_bf16(A[kt][part * 2 + 1]);
                sr  += vr.x  * es0 + vr.y  * es1;
                sr8 += vr8.x * es0 + vr8.y * es1;
            }
        }
#pragma unroll
        for (int off = 1; off < 4; off <<= 1) {
            sr  += __shfl_xor_sync(0xffffffffu, sr,  off);
            sr8 += __shfl_xor_sync(0xffffffffu, sr8, off);
        }
        if (q == 0) {
            g_logZ[b0 + r]     = s + logf(sr);
            g_logZ[b0 + r + 8] = s + logf(sr8);
        }
    }
}

// ---------------------------------------------------------------------------
// Gold-score kernel: one warp per batch; warp-scan for "last valid prev tag".
// ---------------------------------------------------------------------------
__global__ void crf_gold_kernel(const float* __restrict__ em,
                                const float* __restrict__ trans,
                                const void* __restrict__ tags_raw,
                                const int* __restrict__ mask)
{
    const int gw   = (blockIdx.x * blockDim.x + threadIdx.x) >> 5;
    const int lane = threadIdx.x & 31;
    if (gw >= BATCH) return;
    const int b = gw;
    const int is64 = g_tags_is64;
    const long long* tags64 = (const long long*)tags_raw;
    const int*       tags32 = (const int*)tags_raw;

    float acc = 0.0f;
    int carry = START_TAG;

    for (int base = 0; base < TLEN; base += 32) {
        const int t = base + lane;
        const size_t idx = (size_t)b * TLEN + t;
        const int tag = is64 ? (int)tags64[idx] : tags32[idx];
        const int m   = mask[idx];
        const float e = em[(size_t)b * TLEN * NTAGS + (size_t)t * NTAGS + tag];

        int inc = m ? tag : -1;
#pragma unroll
        for (int off = 1; off < 32; off <<= 1) {
            int o = __shfl_up_sync(0xffffffffu, inc, off);
            if (lane >= off && inc < 0) inc = o;
        }
        int prevv = __shfl_up_sync(0xffffffffu, inc, 1);
        int prev  = (lane == 0 || prevv < 0) ? carry : prevv;

        if (m) acc += e + trans[prev * NTAGS + tag];

        int last = __shfl_sync(0xffffffffu, inc, 31);
        if (last >= 0) carry = last;
    }
#pragma unroll
    for (int off = 16; off; off >>= 1)
        acc += __shfl_xor_sync(0xffffffffu, acc, off);
    if (lane == 0)
        g_gold[b] = acc + trans[carry * NTAGS + STOP_TAG];
}

// ---------------------------------------------------------------------------
// Final reduction: mean(logZ - gold) -> d_out[0]
// ---------------------------------------------------------------------------
__global__ void crf_reduce_kernel(float* __restrict__ out)
{
    __shared__ float sh[256];
    const int tid = threadIdx.x;
    float a = 0.0f;
    for (int i = tid; i < BATCH; i += 256)
        a += g_logZ[i] - g_gold[i];
    sh[tid] = a;
    __syncthreads();
    for (int st = 128; st; st >>= 1) {
        if (tid < st) sh[tid] += sh[tid + st];
        __syncthreads();
    }
    if (tid == 0) out[0] = sh[0] / (float)BATCH;
}

// ---------------------------------------------------------------------------
extern "C" void kernel_launch(void* const* d_in, const int* in_sizes, int n_in,
                              void* d_out, int out_size)
{
    const float* em    = (const float*)d_in[0];   // (1024, 512, 64) f32
    const float* trans = (const float*)d_in[1];   // (64, 64) f32
    const void*  tags  = d_in[2];                 // (1024, 512) i32 or i64
    const int*   mask  = (const int*)d_in[3];     // (1024, 512) i32
    float* out = (float*)d_out;

    crf_detect_kernel<<<1, 32>>>((const int*)tags);
    crf_gold_kernel<<<BATCH / 8, 256>>>(em, trans, tags, mask);
    crf_forward_mma_kernel<<<BATCH / FBPC, 128>>>(em, trans, mask);
    crf_reduce_kernel<<<1, 256>>>(out);
}